// round 7
// baseline (speedup 1.0000x reference)
#include <cuda_runtime.h>
#include <cuda_bf16.h>
#include <cstdint>

// ===========================================================================
// TrainableMPOLayer: y = X @ W^T + bias, W = dense collapse of 3-core MPO.
//   1) T01 = core0 x core1
//   2) Whi/Wlo bf16 = split(T01 x core2)     [smem-tiled batched GEMM]
//   3) Xhi/Xlo bf16 = split(x)
//   4) Y = Xhi*Whi + Xhi*Wlo + Xlo*Whi + bias  via mma.sync bf16 (HMMA)
//      512 threads, 16 warps (4Mx4N, warp tile 32x32), BK=64, SW128 swizzle,
//      3-stage cp.async. MMAs issued grouped by split-term so consecutive
//      instructions hit DIFFERENT accumulators (reuse distance 8).
// ===========================================================================

#define KDIM 4096
#define MDIM 1024
#define NDIM 4096

__device__ float          g_T01[256 * 256 * 32];        // 8 MB
__device__ __nv_bfloat16  g_Whi[(size_t)4096 * 4096];   // 32 MB
__device__ __nv_bfloat16  g_Wlo[(size_t)4096 * 4096];   // 32 MB
__device__ __nv_bfloat16  g_Xhi[(size_t)1024 * 4096];   // 8 MB
__device__ __nv_bfloat16  g_Xlo[(size_t)1024 * 4096];   // 8 MB

// ---------------------------------------------------------------------------
// helpers
// ---------------------------------------------------------------------------
__device__ __forceinline__ uint32_t smem_u32(const void* p) {
    uint32_t a;
    asm("{ .reg .u64 t; cvta.to.shared.u64 t, %1; cvt.u32.u64 %0, t; }"
        : "=r"(a) : "l"(p));
    return a;
}

__device__ __forceinline__ void cpasync16(uint32_t dst, const void* src) {
    asm volatile("cp.async.cg.shared.global [%0], [%1], 16;"
                 :: "r"(dst), "l"(src) : "memory");
}

__device__ __forceinline__ void ldsm4(uint32_t& r0, uint32_t& r1,
                                      uint32_t& r2, uint32_t& r3, uint32_t a) {
    asm volatile("ldmatrix.sync.aligned.m8n8.x4.shared.b16 {%0,%1,%2,%3}, [%4];"
                 : "=r"(r0), "=r"(r1), "=r"(r2), "=r"(r3) : "r"(a));
}

__device__ __forceinline__ void mma16816(float* d, const uint32_t* a,
                                         uint32_t b0, uint32_t b1) {
    asm volatile(
        "mma.sync.aligned.m16n8k16.row.col.f32.bf16.bf16.f32 "
        "{%0,%1,%2,%3}, {%4,%5,%6,%7}, {%8,%9}, {%0,%1,%2,%3};"
        : "+f"(d[0]), "+f"(d[1]), "+f"(d[2]), "+f"(d[3])
        : "r"(a[0]), "r"(a[1]), "r"(a[2]), "r"(a[3]), "r"(b0), "r"(b1));
}

// ---------------------------------------------------------------------------
// Kernel 1: T01[ii, jj, r2] = sum_r1 core0[i1,j1,r1] * core1[r1,i2,j2,r2]
// ---------------------------------------------------------------------------
__global__ void build_t01_kernel(const float* __restrict__ c0,
                                 const float* __restrict__ c1) {
    int idx = blockIdx.x * blockDim.x + threadIdx.x;   // 0 .. 256*256*8-1
    int r2q = idx & 7;
    int jj  = (idx >> 3) & 255;
    int ii  = idx >> 11;
    int j1 = jj >> 4, j2 = jj & 15;
    int i1 = ii >> 4, i2 = ii & 15;

    const float*  a = c0 + (i1 * 16 + j1) * 32;
    const float4* b = (const float4*)(c1 + i2 * 512 + j2 * 32 + r2q * 4);

    float4 s = make_float4(0.f, 0.f, 0.f, 0.f);
#pragma unroll
    for (int r1 = 0; r1 < 32; ++r1) {
        float  av = a[r1];
        float4 bv = b[(size_t)r1 * 2048];
        s.x += av * bv.x; s.y += av * bv.y; s.z += av * bv.z; s.w += av * bv.w;
    }
    *(float4*)(g_T01 + (size_t)idx * 4) = s;
}

// ---------------------------------------------------------------------------
// Kernel 2: per block: one ii (16 W-rows), 64 jj (1024 W-cols), smem-tiled.
// ---------------------------------------------------------------------------
#define T01T_PITCH 68

__global__ __launch_bounds__(256)
void build_w_kernel(const float* __restrict__ c2) {
    __shared__ __align__(16) float c2s[32 * 256];
    __shared__ __align__(16) float t01t[32 * T01T_PITCH];

    const int tid = threadIdx.x;
    const int ii  = blockIdx.y;
    const int jjb = blockIdx.x * 64;

#pragma unroll
    for (int c = tid; c < 2048; c += 256)
        *(float4*)&c2s[c * 4] = *(const float4*)&c2[c * 4];
#pragma unroll
    for (int c = tid; c < 2048; c += 256) {
        int jj = c >> 5, r2 = c & 31;
        t01t[r2 * T01T_PITCH + jj] = g_T01[((size_t)ii * 256 + jjb + jj) * 32 + r2];
    }
    __syncthreads();

    const int jjg = tid >> 4;
    const int i3  = tid & 15;

    float acc[4][16];
#pragma unroll
    for (int a = 0; a < 4; ++a)
#pragma unroll
        for (int b = 0; b < 16; ++b) acc[a][b] = 0.f;

#pragma unroll
    for (int r2 = 0; r2 < 32; ++r2) {
        float4 tv = *(const float4*)&t01t[r2 * T01T_PITCH + jjg * 4];
        const float* crow = &c2s[r2 * 256 + i3 * 16];
        float4 cv0 = *(const float4*)&crow[0];
        float4 cv1 = *(const float4*)&crow[4];
        float4 cv2 = *(const float4*)&crow[8];
        float4 cv3 = *(const float4*)&crow[12];
        float cva[16] = {cv0.x, cv0.y, cv0.z, cv0.w, cv1.x, cv1.y, cv1.z, cv1.w,
                         cv2.x, cv2.y, cv2.z, cv2.w, cv3.x, cv3.y, cv3.z, cv3.w};
        float tva[4] = {tv.x, tv.y, tv.z, tv.w};
#pragma unroll
        for (int a = 0; a < 4; ++a)
#pragma unroll
            for (int b = 0; b < 16; ++b)
                acc[a][b] += tva[a] * cva[b];
    }

    const size_t rowoff = (size_t)(ii * 16 + i3) * 4096;
#pragma unroll
    for (int a = 0; a < 4; ++a) {
        const size_t o = rowoff + (size_t)(jjb + jjg * 4 + a) * 16;
        __nv_bfloat162 hibuf[8], lobuf[8];
#pragma unroll
        for (int p = 0; p < 8; ++p) {
            float v0 = acc[a][2 * p], v1 = acc[a][2 * p + 1];
            __nv_bfloat16 h0 = __float2bfloat16(v0);
            __nv_bfloat16 h1 = __float2bfloat16(v1);
            hibuf[p] = __nv_bfloat162(h0, h1);
            lobuf[p] = __nv_bfloat162(__float2bfloat16(v0 - __bfloat162float(h0)),
                                      __float2bfloat16(v1 - __bfloat162float(h1)));
        }
        *(uint4*)(g_Whi + o)     = *(uint4*)&hibuf[0];
        *(uint4*)(g_Whi + o + 8) = *(uint4*)&hibuf[4];
        *(uint4*)(g_Wlo + o)     = *(uint4*)&lobuf[0];
        *(uint4*)(g_Wlo + o + 8) = *(uint4*)&lobuf[4];
    }
}

// ---------------------------------------------------------------------------
// Kernel 3: split X into bf16 hi/lo
// ---------------------------------------------------------------------------
__global__ void split_x_kernel(const float* __restrict__ x) {
    int idx = blockIdx.x * blockDim.x + threadIdx.x;
    float4 v = ((const float4*)x)[idx];
    __nv_bfloat16 h0 = __float2bfloat16(v.x);
    __nv_bfloat16 h1 = __float2bfloat16(v.y);
    __nv_bfloat16 h2 = __float2bfloat16(v.z);
    __nv_bfloat16 h3 = __float2bfloat16(v.w);
    __nv_bfloat16 l0 = __float2bfloat16(v.x - __bfloat162float(h0));
    __nv_bfloat16 l1 = __float2bfloat16(v.y - __bfloat162float(h1));
    __nv_bfloat16 l2 = __float2bfloat16(v.z - __bfloat162float(h2));
    __nv_bfloat16 l3 = __float2bfloat16(v.w - __bfloat162float(h3));
    __nv_bfloat162* Hp = (__nv_bfloat162*)g_Xhi;
    __nv_bfloat162* Lp = (__nv_bfloat162*)g_Xlo;
    Hp[idx * 2 + 0] = __nv_bfloat162(h0, h1);
    Hp[idx * 2 + 1] = __nv_bfloat162(h2, h3);
    Lp[idx * 2 + 0] = __nv_bfloat162(l0, l1);
    Lp[idx * 2 + 1] = __nv_bfloat162(l2, l3);
}

// ---------------------------------------------------------------------------
// Kernel 4: HMMA GEMM. C[1024,4096] = Xsplit @ Wsplit^T + bias
// CTA 128x128, BK=64, SW128 swizzle, 3-stage cp.async, 512 threads.
// 16 warps = 4(M) x 4(N); warp tile 32x32. Term-grouped MMA issue.
// ---------------------------------------------------------------------------
#define GBM 128
#define GBN 128
#define GBK 64
#define NKT (KDIM / GBK)            // 64
#define ST_AHI 0
#define ST_ALO 16384
#define ST_BHI 32768
#define ST_BLO 49152
#define STAGE_BYTES 65536
#define NSTAGE 3
#define SMEM_TOTAL (NSTAGE * STAGE_BYTES)   // 192 KB
#define NTHREADS 512

__device__ __forceinline__ void load_stage(uint32_t st, int bm, int bn,
                                           int kt, int tid) {
    const size_t krow = (size_t)kt * 128;     // byte offset within K row
#pragma unroll
    for (int c = tid; c < 1024; c += NTHREADS) {   // 128 rows x 8 16B-chunks
        int row = c >> 3, ch = c & 7;
        uint32_t so = (uint32_t)(row * 128 + ch * 16);
        so ^= (so >> 3) & 0x70;
        const size_t ga = (size_t)(bm + row) * 8192 + krow + ch * 16;
        const size_t gb = (size_t)(bn + row) * 8192 + krow + ch * 16;
        cpasync16(st + ST_AHI + so, (const char*)g_Xhi + ga);
        cpasync16(st + ST_ALO + so, (const char*)g_Xlo + ga);
        cpasync16(st + ST_BHI + so, (const char*)g_Whi + gb);
        cpasync16(st + ST_BLO + so, (const char*)g_Wlo + gb);
    }
}

__global__ __launch_bounds__(NTHREADS, 1)
void gemm_mma_kernel(const float* __restrict__ bias, float* __restrict__ C) {
    extern __shared__ __align__(1024) char smem[];
    const uint32_t sbase = smem_u32(smem);
    const int tid  = threadIdx.x;
    const int wid  = tid >> 5;
    const int lane = tid & 31;
    const int wm = wid & 3;          // 4 M-warps (32 rows each)
    const int wn = wid >> 2;         // 4 N-warps (32 cols each)
    const int bm = blockIdx.y * GBM;
    const int bn = blockIdx.x * GBN;

    const int lrow   = lane & 15;
    const int lchunk = (lane >> 4) * 16;

    uint32_t a_base[2], a_mask[2];
#pragma unroll
    for (int mt = 0; mt < 2; ++mt) {
        int r = wm * 32 + mt * 16 + lrow;
        a_base[mt] = (uint32_t)(r * 128);
        a_mask[mt] = (uint32_t)((r & 7) << 4);
    }
    uint32_t b_base[2], b_mask[2];
#pragma unroll
    for (int c = 0; c < 2; ++c) {
        int r = wn * 32 + c * 16 + lrow;
        b_base[c] = (uint32_t)(r * 128);
        b_mask[c] = (uint32_t)((r & 7) << 4);
    }

    float acc[2][4][4];
#pragma unroll
    for (int mt = 0; mt < 2; ++mt)
#pragma unroll
        for (int nt = 0; nt < 4; ++nt)
#pragma unroll
            for (int e = 0; e < 4; ++e) acc[mt][nt][e] = 0.f;

    // prologue: stages 0 and 1 in flight
    load_stage(sbase + 0 * STAGE_BYTES, bm, bn, 0, tid);
    asm volatile("cp.async.commit_group;" ::: "memory");
    load_stage(sbase + 1 * STAGE_BYTES, bm, bn, 1, tid);
    asm volatile("cp.async.commit_group;" ::: "memory");

    int slot = 0;
    for (int kt = 0; kt < NKT; ++kt) {
        if (kt + 1 < NKT)
            asm volatile("cp.async.wait_group 1;" ::: "memory");
        else
            asm volatile("cp.async.wait_group 0;" ::: "memory");
        __syncthreads();

        if (kt + 2 < NKT) {
            int ns = slot + 2; if (ns >= NSTAGE) ns -= NSTAGE;
            load_stage(sbase + ns * STAGE_BYTES, bm, bn, kt + 2, tid);
            asm volatile("cp.async.commit_group;" ::: "memory");
        }

        const uint32_t st = sbase + slot * STAGE_BYTES;
#pragma unroll
        for (int ks = 0; ks < 4; ++ks) {
            const uint32_t kb = (uint32_t)(ks * 32);
            // load ALL fragments for this K16 step
            uint32_t ah[2][4], al[2][4], bh[2][4], bl[2][4];
#pragma unroll
            for (int mt = 0; mt < 2; ++mt) {
                uint32_t col = (lchunk + kb) ^ a_mask[mt];
                ldsm4(ah[mt][0], ah[mt][1], ah[mt][2], ah[mt][3],
                      st + ST_AHI + a_base[mt] + col);
                ldsm4(al[mt][0], al[mt][1], al[mt][2], al[mt][3],
                      st + ST_ALO + a_base[mt] + col);
            }
#pragma unroll
            for (int c = 0; c < 2; ++c) {
                uint32_t col = (lchunk + kb) ^ b_mask[c];
                ldsm4(bh[c][0], bh[c][1], bh[c][2], bh[c][3],
                      st + ST_BHI + b_base[c] + col);
                ldsm4(bl[c][0], bl[c][1], bl[c][2], bl[c][3],
                      st + ST_BLO + b_base[c] + col);
            }
            // term-grouped issue: 8 independent MMAs per term ->
            // same-accumulator reuse distance = 8 instructions
#pragma unroll
            for (int mt = 0; mt < 2; ++mt)           // term hh
#pragma unroll
                for (int c = 0; c < 2; ++c)
#pragma unroll
                    for (int o = 0; o < 2; ++o)
                        mma16816(acc[mt][c * 2 + o], ah[mt], bh[c][o], bh[c][o + 2]);
#pragma unroll
            for (int mt = 0; mt < 2; ++mt)           // term hl
#pragma unroll
                for (int c = 0; c < 2; ++c)
#pragma unroll
                    for (int o = 0; o < 2; ++o)
                        mma16816(acc[mt][c * 2 + o], ah[mt], bl[c][o], bl[c][o + 2]);
#pragma unroll
            for (int mt = 0; mt < 2; ++mt)           // term lh
#pragma unroll
                for (int c = 0; c < 2; ++c)
#pragma unroll
                    for (int o = 0; o < 2; ++o)
                        mma16816(acc[mt][c * 2 + o], al[mt], bh[c][o], bh[c][o + 2]);
        }
        ++slot; if (slot >= NSTAGE) slot = 0;
    }

    // epilogue
    const int gq = lane >> 2, rq = lane & 3;
#pragma unroll
    for (int mt = 0; mt < 2; ++mt) {
        const int r0 = bm + wm * 32 + mt * 16 + gq;
#pragma unroll
        for (int nt = 0; nt < 4; ++nt) {
            const int col = bn + wn * 32 + nt * 8 + rq * 2;
            float2 bv = *(const float2*)&bias[col];
            float2 o0 = make_float2(acc[mt][nt][0] + bv.x, acc[mt][nt][1] + bv.y);
            float2 o1 = make_float2(acc[mt][nt][2] + bv.x, acc[mt][nt][3] + bv.y);
            *(float2*)&C[(size_t)r0 * NDIM + col]       = o0;
            *(float2*)&C[(size_t)(r0 + 8) * NDIM + col] = o1;
        }
    }
}

// ---------------------------------------------------------------------------
extern "C" void kernel_launch(void* const* d_in, const int* in_sizes, int n_in,
                              void* d_out, int out_size) {
    const float* x     = (const float*)d_in[0];
    const float* core0 = (const float*)d_in[1];
    const float* core1 = (const float*)d_in[2];
    const float* core2 = (const float*)d_in[3];
    const float* bias  = (const float*)d_in[4];
    float* out = (float*)d_out;

    build_t01_kernel<<<(256 * 256 * 8) / 256, 256>>>(core0, core1);
    build_w_kernel<<<dim3(4, 256), 256>>>(core2);
    split_x_kernel<<<(MDIM * KDIM / 4) / 256, 256>>>(x);

    cudaFuncSetAttribute(gemm_mma_kernel,
                         cudaFuncAttributeMaxDynamicSharedMemorySize, SMEM_TOTAL);
    gemm_mma_kernel<<<dim3(NDIM / GBN, MDIM / GBM), NTHREADS, SMEM_TOTAL>>>(bias, out);
}

// round 8
// speedup vs baseline: 1.0001x; 1.0001x over previous
#include <cuda_runtime.h>
#include <cuda_bf16.h>
#include <cstdint>

// ===========================================================================
// TrainableMPOLayer: y = X @ W^T + bias, W = dense collapse of 3-core MPO.
//   1) T01 = core0 x core1
//   2) Whi/Wlo bf16 = split(T01 x core2)     [smem-tiled batched GEMM]
//   3) Xhi/Xlo bf16 = split(x)
//   4) Y = Xhi*Whi + Xhi*Wlo + Xlo*Whi + bias  via mma.sync bf16 (HMMA)
//      512 threads, 16 warps (4Mx4N, warp tile 32x32), BK=64, SW128 swizzle,
//      3-stage cp.async. NEW: warp phase-staggered K16 order + register
//      fragment double-buffering (ldsm of step i+1 issued before MMAs of i).
// ===========================================================================

#define KDIM 4096
#define MDIM 1024
#define NDIM 4096

__device__ float          g_T01[256 * 256 * 32];        // 8 MB
__device__ __nv_bfloat16  g_Whi[(size_t)4096 * 4096];   // 32 MB
__device__ __nv_bfloat16  g_Wlo[(size_t)4096 * 4096];   // 32 MB
__device__ __nv_bfloat16  g_Xhi[(size_t)1024 * 4096];   // 8 MB
__device__ __nv_bfloat16  g_Xlo[(size_t)1024 * 4096];   // 8 MB

// ---------------------------------------------------------------------------
// helpers
// ---------------------------------------------------------------------------
__device__ __forceinline__ uint32_t smem_u32(const void* p) {
    uint32_t a;
    asm("{ .reg .u64 t; cvta.to.shared.u64 t, %1; cvt.u32.u64 %0, t; }"
        : "=r"(a) : "l"(p));
    return a;
}

__device__ __forceinline__ void cpasync16(uint32_t dst, const void* src) {
    asm volatile("cp.async.cg.shared.global [%0], [%1], 16;"
                 :: "r"(dst), "l"(src) : "memory");
}

__device__ __forceinline__ void ldsm4(uint32_t& r0, uint32_t& r1,
                                      uint32_t& r2, uint32_t& r3, uint32_t a) {
    asm volatile("ldmatrix.sync.aligned.m8n8.x4.shared.b16 {%0,%1,%2,%3}, [%4];"
                 : "=r"(r0), "=r"(r1), "=r"(r2), "=r"(r3) : "r"(a));
}

__device__ __forceinline__ void mma16816(float* d, const uint32_t* a,
                                         uint32_t b0, uint32_t b1) {
    asm volatile(
        "mma.sync.aligned.m16n8k16.row.col.f32.bf16.bf16.f32 "
        "{%0,%1,%2,%3}, {%4,%5,%6,%7}, {%8,%9}, {%0,%1,%2,%3};"
        : "+f"(d[0]), "+f"(d[1]), "+f"(d[2]), "+f"(d[3])
        : "r"(a[0]), "r"(a[1]), "r"(a[2]), "r"(a[3]), "r"(b0), "r"(b1));
}

// ---------------------------------------------------------------------------
// Kernel 1: T01[ii, jj, r2] = sum_r1 core0[i1,j1,r1] * core1[r1,i2,j2,r2]
// ---------------------------------------------------------------------------
__global__ void build_t01_kernel(const float* __restrict__ c0,
                                 const float* __restrict__ c1) {
    int idx = blockIdx.x * blockDim.x + threadIdx.x;   // 0 .. 256*256*8-1
    int r2q = idx & 7;
    int jj  = (idx >> 3) & 255;
    int ii  = idx >> 11;
    int j1 = jj >> 4, j2 = jj & 15;
    int i1 = ii >> 4, i2 = ii & 15;

    const float*  a = c0 + (i1 * 16 + j1) * 32;
    const float4* b = (const float4*)(c1 + i2 * 512 + j2 * 32 + r2q * 4);

    float4 s = make_float4(0.f, 0.f, 0.f, 0.f);
#pragma unroll
    for (int r1 = 0; r1 < 32; ++r1) {
        float  av = a[r1];
        float4 bv = b[(size_t)r1 * 2048];
        s.x += av * bv.x; s.y += av * bv.y; s.z += av * bv.z; s.w += av * bv.w;
    }
    *(float4*)(g_T01 + (size_t)idx * 4) = s;
}

// ---------------------------------------------------------------------------
// Kernel 2: per block: one ii (16 W-rows), 64 jj (1024 W-cols), smem-tiled.
// ---------------------------------------------------------------------------
#define T01T_PITCH 68

__global__ __launch_bounds__(256)
void build_w_kernel(const float* __restrict__ c2) {
    __shared__ __align__(16) float c2s[32 * 256];
    __shared__ __align__(16) float t01t[32 * T01T_PITCH];

    const int tid = threadIdx.x;
    const int ii  = blockIdx.y;
    const int jjb = blockIdx.x * 64;

#pragma unroll
    for (int c = tid; c < 2048; c += 256)
        *(float4*)&c2s[c * 4] = *(const float4*)&c2[c * 4];
#pragma unroll
    for (int c = tid; c < 2048; c += 256) {
        int jj = c >> 5, r2 = c & 31;
        t01t[r2 * T01T_PITCH + jj] = g_T01[((size_t)ii * 256 + jjb + jj) * 32 + r2];
    }
    __syncthreads();

    const int jjg = tid >> 4;
    const int i3  = tid & 15;

    float acc[4][16];
#pragma unroll
    for (int a = 0; a < 4; ++a)
#pragma unroll
        for (int b = 0; b < 16; ++b) acc[a][b] = 0.f;

#pragma unroll
    for (int r2 = 0; r2 < 32; ++r2) {
        float4 tv = *(const float4*)&t01t[r2 * T01T_PITCH + jjg * 4];
        const float* crow = &c2s[r2 * 256 + i3 * 16];
        float4 cv0 = *(const float4*)&crow[0];
        float4 cv1 = *(const float4*)&crow[4];
        float4 cv2 = *(const float4*)&crow[8];
        float4 cv3 = *(const float4*)&crow[12];
        float cva[16] = {cv0.x, cv0.y, cv0.z, cv0.w, cv1.x, cv1.y, cv1.z, cv1.w,
                         cv2.x, cv2.y, cv2.z, cv2.w, cv3.x, cv3.y, cv3.z, cv3.w};
        float tva[4] = {tv.x, tv.y, tv.z, tv.w};
#pragma unroll
        for (int a = 0; a < 4; ++a)
#pragma unroll
            for (int b = 0; b < 16; ++b)
                acc[a][b] += tva[a] * cva[b];
    }

    const size_t rowoff = (size_t)(ii * 16 + i3) * 4096;
#pragma unroll
    for (int a = 0; a < 4; ++a) {
        const size_t o = rowoff + (size_t)(jjb + jjg * 4 + a) * 16;
        __nv_bfloat162 hibuf[8], lobuf[8];
#pragma unroll
        for (int p = 0; p < 8; ++p) {
            float v0 = acc[a][2 * p], v1 = acc[a][2 * p + 1];
            __nv_bfloat16 h0 = __float2bfloat16(v0);
            __nv_bfloat16 h1 = __float2bfloat16(v1);
            hibuf[p] = __nv_bfloat162(h0, h1);
            lobuf[p] = __nv_bfloat162(__float2bfloat16(v0 - __bfloat162float(h0)),
                                      __float2bfloat16(v1 - __bfloat162float(h1)));
        }
        *(uint4*)(g_Whi + o)     = *(uint4*)&hibuf[0];
        *(uint4*)(g_Whi + o + 8) = *(uint4*)&hibuf[4];
        *(uint4*)(g_Wlo + o)     = *(uint4*)&lobuf[0];
        *(uint4*)(g_Wlo + o + 8) = *(uint4*)&lobuf[4];
    }
}

// ---------------------------------------------------------------------------
// Kernel 3: split X into bf16 hi/lo
// ---------------------------------------------------------------------------
__global__ void split_x_kernel(const float* __restrict__ x) {
    int idx = blockIdx.x * blockDim.x + threadIdx.x;
    float4 v = ((const float4*)x)[idx];
    __nv_bfloat16 h0 = __float2bfloat16(v.x);
    __nv_bfloat16 h1 = __float2bfloat16(v.y);
    __nv_bfloat16 h2 = __float2bfloat16(v.z);
    __nv_bfloat16 h3 = __float2bfloat16(v.w);
    __nv_bfloat16 l0 = __float2bfloat16(v.x - __bfloat162float(h0));
    __nv_bfloat16 l1 = __float2bfloat16(v.y - __bfloat162float(h1));
    __nv_bfloat16 l2 = __float2bfloat16(v.z - __bfloat162float(h2));
    __nv_bfloat16 l3 = __float2bfloat16(v.w - __bfloat162float(h3));
    __nv_bfloat162* Hp = (__nv_bfloat162*)g_Xhi;
    __nv_bfloat162* Lp = (__nv_bfloat162*)g_Xlo;
    Hp[idx * 2 + 0] = __nv_bfloat162(h0, h1);
    Hp[idx * 2 + 1] = __nv_bfloat162(h2, h3);
    Lp[idx * 2 + 0] = __nv_bfloat162(l0, l1);
    Lp[idx * 2 + 1] = __nv_bfloat162(l2, l3);
}

// ---------------------------------------------------------------------------
// Kernel 4: HMMA GEMM. C[1024,4096] = Xsplit @ Wsplit^T + bias
// CTA 128x128, BK=64, SW128 swizzle, 3-stage cp.async, 512 threads.
// 16 warps = 4(M) x 4(N); warp tile 32x32. Phase-staggered K16 order +
// register frag double-buffering.
// ---------------------------------------------------------------------------
#define GBM 128
#define GBN 128
#define GBK 64
#define NKT (KDIM / GBK)            // 64
#define ST_AHI 0
#define ST_ALO 16384
#define ST_BHI 32768
#define ST_BLO 49152
#define STAGE_BYTES 65536
#define NSTAGE 3
#define SMEM_TOTAL (NSTAGE * STAGE_BYTES)   // 192 KB
#define NTHREADS 512

struct Frags {
    uint32_t ah[2][4], al[2][4], bh[2][4], bl[2][4];
};

__device__ __forceinline__ void load_frags(Frags& f, uint32_t st, int ksel,
                                           uint32_t lchunk,
                                           const uint32_t* a_base,
                                           const uint32_t* a_mask,
                                           const uint32_t* b_base,
                                           const uint32_t* b_mask) {
    const uint32_t kb = (uint32_t)(ksel * 32);
#pragma unroll
    for (int mt = 0; mt < 2; ++mt) {
        uint32_t col = (lchunk + kb) ^ a_mask[mt];
        ldsm4(f.ah[mt][0], f.ah[mt][1], f.ah[mt][2], f.ah[mt][3],
              st + ST_AHI + a_base[mt] + col);
        ldsm4(f.al[mt][0], f.al[mt][1], f.al[mt][2], f.al[mt][3],
              st + ST_ALO + a_base[mt] + col);
    }
#pragma unroll
    for (int c = 0; c < 2; ++c) {
        uint32_t col = (lchunk + kb) ^ b_mask[c];
        ldsm4(f.bh[c][0], f.bh[c][1], f.bh[c][2], f.bh[c][3],
              st + ST_BHI + b_base[c] + col);
        ldsm4(f.bl[c][0], f.bl[c][1], f.bl[c][2], f.bl[c][3],
              st + ST_BLO + b_base[c] + col);
    }
}

__device__ __forceinline__ void mma_frags(float acc[2][4][4], const Frags& f) {
    // term-grouped: 8 independent accumulators per term
#pragma unroll
    for (int mt = 0; mt < 2; ++mt)
#pragma unroll
        for (int c = 0; c < 2; ++c)
#pragma unroll
            for (int o = 0; o < 2; ++o)
                mma16816(acc[mt][c * 2 + o], f.ah[mt], f.bh[c][o], f.bh[c][o + 2]);
#pragma unroll
    for (int mt = 0; mt < 2; ++mt)
#pragma unroll
        for (int c = 0; c < 2; ++c)
#pragma unroll
            for (int o = 0; o < 2; ++o)
                mma16816(acc[mt][c * 2 + o], f.ah[mt], f.bl[c][o], f.bl[c][o + 2]);
#pragma unroll
    for (int mt = 0; mt < 2; ++mt)
#pragma unroll
        for (int c = 0; c < 2; ++c)
#pragma unroll
            for (int o = 0; o < 2; ++o)
                mma16816(acc[mt][c * 2 + o], f.al[mt], f.bh[c][o], f.bh[c][o + 2]);
}

__device__ __forceinline__ void load_stage(uint32_t st, int bm, int bn,
                                           int kt, int tid) {
    const size_t krow = (size_t)kt * 128;     // byte offset within K row
#pragma unroll
    for (int c = tid; c < 1024; c += NTHREADS) {   // 128 rows x 8 16B-chunks
        int row = c >> 3, ch = c & 7;
        uint32_t so = (uint32_t)(row * 128 + ch * 16);
        so ^= (so >> 3) & 0x70;
        const size_t ga = (size_t)(bm + row) * 8192 + krow + ch * 16;
        const size_t gb = (size_t)(bn + row) * 8192 + krow + ch * 16;
        cpasync16(st + ST_AHI + so, (const char*)g_Xhi + ga);
        cpasync16(st + ST_ALO + so, (const char*)g_Xlo + ga);
        cpasync16(st + ST_BHI + so, (const char*)g_Whi + gb);
        cpasync16(st + ST_BLO + so, (const char*)g_Wlo + gb);
    }
}

__global__ __launch_bounds__(NTHREADS, 1)
void gemm_mma_kernel(const float* __restrict__ bias, float* __restrict__ C) {
    extern __shared__ __align__(1024) char smem[];
    const uint32_t sbase = smem_u32(smem);
    const int tid  = threadIdx.x;
    const int wid  = tid >> 5;
    const int lane = tid & 31;
    const int wm = wid & 3;          // 4 M-warps (32 rows each)
    const int wn = wid >> 2;         // 4 N-warps (32 cols each)
    const int ph = wid & 3;          // per-warp K16 phase offset
    const int bm = blockIdx.y * GBM;
    const int bn = blockIdx.x * GBN;

    const int lrow   = lane & 15;
    const uint32_t lchunk = (uint32_t)((lane >> 4) * 16);

    uint32_t a_base[2], a_mask[2];
#pragma unroll
    for (int mt = 0; mt < 2; ++mt) {
        int r = wm * 32 + mt * 16 + lrow;
        a_base[mt] = (uint32_t)(r * 128);
        a_mask[mt] = (uint32_t)((r & 7) << 4);
    }
    uint32_t b_base[2], b_mask[2];
#pragma unroll
    for (int c = 0; c < 2; ++c) {
        int r = wn * 32 + c * 16 + lrow;
        b_base[c] = (uint32_t)(r * 128);
        b_mask[c] = (uint32_t)((r & 7) << 4);
    }

    float acc[2][4][4];
#pragma unroll
    for (int mt = 0; mt < 2; ++mt)
#pragma unroll
        for (int nt = 0; nt < 4; ++nt)
#pragma unroll
            for (int e = 0; e < 4; ++e) acc[mt][nt][e] = 0.f;

    // prologue: stages 0 and 1 in flight
    load_stage(sbase + 0 * STAGE_BYTES, bm, bn, 0, tid);
    asm volatile("cp.async.commit_group;" ::: "memory");
    load_stage(sbase + 1 * STAGE_BYTES, bm, bn, 1, tid);
    asm volatile("cp.async.commit_group;" ::: "memory");

    Frags fr[2];
    int slot = 0;
    for (int kt = 0; kt < NKT; ++kt) {
        if (kt + 1 < NKT)
            asm volatile("cp.async.wait_group 1;" ::: "memory");
        else
            asm volatile("cp.async.wait_group 0;" ::: "memory");
        __syncthreads();

        if (kt + 2 < NKT) {
            int ns = slot + 2; if (ns >= NSTAGE) ns -= NSTAGE;
            load_stage(sbase + ns * STAGE_BYTES, bm, bn, kt + 2, tid);
            asm volatile("cp.async.commit_group;" ::: "memory");
        }

        const uint32_t st = sbase + slot * STAGE_BYTES;
        // software-pipelined, phase-staggered K16 steps
        load_frags(fr[0], st, ph, lchunk, a_base, a_mask, b_base, b_mask);
#pragma unroll
        for (int i = 0; i < 4; ++i) {
            if (i < 3)
                load_frags(fr[(i + 1) & 1], st, (ph + i + 1) & 3, lchunk,
                           a_base, a_mask, b_base, b_mask);
            mma_frags(acc, fr[i & 1]);
        }
        ++slot; if (slot >= NSTAGE) slot = 0;
    }

    // epilogue
    const int gq = lane >> 2, rq = lane & 3;
#pragma unroll
    for (int mt = 0; mt < 2; ++mt) {
        const int r0 = bm + wm * 32 + mt * 16 + gq;
#pragma unroll
        for (int nt = 0; nt < 4; ++nt) {
            const int col = bn + wn * 32 + nt * 8 + rq * 2;
            float2 bv = *(const float2*)&bias[col];
            float2 o0 = make_float2(acc[mt][nt][0] + bv.x, acc[mt][nt][1] + bv.y);
            float2 o1 = make_float2(acc[mt][nt][2] + bv.x, acc[mt][nt][3] + bv.y);
            *(float2*)&C[(size_t)r0 * NDIM + col]       = o0;
            *(float2*)&C[(size_t)(r0 + 8) * NDIM + col] = o1;
        }
    }
}

// ---------------------------------------------------------------------------
extern "C" void kernel_launch(void* const* d_in, const int* in_sizes, int n_in,
                              void* d_out, int out_size) {
    const float* x     = (const float*)d_in[0];
    const float* core0 = (const float*)d_in[1];
    const float* core1 = (const float*)d_in[2];
    const float* core2 = (const float*)d_in[3];
    const float* bias  = (const float*)d_in[4];
    float* out = (float*)d_out;

    build_t01_kernel<<<(256 * 256 * 8) / 256, 256>>>(core0, core1);
    build_w_kernel<<<dim3(4, 256), 256>>>(core2);
    split_x_kernel<<<(MDIM * KDIM / 4) / 256, 256>>>(x);

    cudaFuncSetAttribute(gemm_mma_kernel,
                         cudaFuncAttributeMaxDynamicSharedMemorySize, SMEM_TOTAL);
    gemm_mma_kernel<<<dim3(NDIM / GBN, MDIM / GBM), NTHREADS, SMEM_TOTAL>>>(bias, out);
}

// round 9
// speedup vs baseline: 1.2637x; 1.2636x over previous
#include <cuda_runtime.h>
#include <cuda_fp16.h>
#include <cstdint>

// ===========================================================================
// TrainableMPOLayer: y = X @ W^T + bias, W = dense collapse of 3-core MPO.
//   1) T01 = core0 x core1                     (fp32)
//   2) Whf = fp16(W * 2^14)                    (smem-tiled batched GEMM)
//   3) Xhf = fp16(x)
//   4) Y = (Xhf @ Whf^T) * 2^-14 + bias        single-term fp16 HMMA GEMM
// fp16 1-term: norm rel err ~2-3e-4 < 1e-3. W scaled by exact 2^14 to avoid
// fp16 subnormals (W entries ~3e-5); scale undone exactly in epilogue.
// ===========================================================================

#define KDIM 4096
#define MDIM 1024
#define NDIM 4096
#define WSCALE 16384.0f
#define WINV   (1.0f / 16384.0f)

__device__ float   g_T01[256 * 256 * 32];      // 8 MB
__device__ __half  g_Whf[(size_t)4096 * 4096]; // 32 MB (W * 2^14)
__device__ __half  g_Xhf[(size_t)1024 * 4096]; // 8 MB

// ---------------------------------------------------------------------------
// helpers
// ---------------------------------------------------------------------------
__device__ __forceinline__ uint32_t smem_u32(const void* p) {
    uint32_t a;
    asm("{ .reg .u64 t; cvta.to.shared.u64 t, %1; cvt.u32.u64 %0, t; }"
        : "=r"(a) : "l"(p));
    return a;
}

__device__ __forceinline__ void cpasync16(uint32_t dst, const void* src) {
    asm volatile("cp.async.cg.shared.global [%0], [%1], 16;"
                 :: "r"(dst), "l"(src) : "memory");
}

__device__ __forceinline__ void ldsm4(uint32_t& r0, uint32_t& r1,
                                      uint32_t& r2, uint32_t& r3, uint32_t a) {
    asm volatile("ldmatrix.sync.aligned.m8n8.x4.shared.b16 {%0,%1,%2,%3}, [%4];"
                 : "=r"(r0), "=r"(r1), "=r"(r2), "=r"(r3) : "r"(a));
}

__device__ __forceinline__ void mma16816(float* d, const uint32_t* a,
                                         uint32_t b0, uint32_t b1) {
    asm volatile(
        "mma.sync.aligned.m16n8k16.row.col.f32.f16.f16.f32 "
        "{%0,%1,%2,%3}, {%4,%5,%6,%7}, {%8,%9}, {%0,%1,%2,%3};"
        : "+f"(d[0]), "+f"(d[1]), "+f"(d[2]), "+f"(d[3])
        : "r"(a[0]), "r"(a[1]), "r"(a[2]), "r"(a[3]), "r"(b0), "r"(b1));
}

// ---------------------------------------------------------------------------
// Kernel 1: T01[ii, jj, r2] = sum_r1 core0[i1,j1,r1] * core1[r1,i2,j2,r2]
// ---------------------------------------------------------------------------
__global__ void build_t01_kernel(const float* __restrict__ c0,
                                 const float* __restrict__ c1) {
    int idx = blockIdx.x * blockDim.x + threadIdx.x;   // 0 .. 256*256*8-1
    int r2q = idx & 7;
    int jj  = (idx >> 3) & 255;
    int ii  = idx >> 11;
    int j1 = jj >> 4, j2 = jj & 15;
    int i1 = ii >> 4, i2 = ii & 15;

    const float*  a = c0 + (i1 * 16 + j1) * 32;
    const float4* b = (const float4*)(c1 + i2 * 512 + j2 * 32 + r2q * 4);

    float4 s = make_float4(0.f, 0.f, 0.f, 0.f);
#pragma unroll
    for (int r1 = 0; r1 < 32; ++r1) {
        float  av = a[r1];
        float4 bv = b[(size_t)r1 * 2048];
        s.x += av * bv.x; s.y += av * bv.y; s.z += av * bv.z; s.w += av * bv.w;
    }
    *(float4*)(g_T01 + (size_t)idx * 4) = s;
}

// ---------------------------------------------------------------------------
// Kernel 2: W[i,j] = sum_r2 T01[ihi,jhi,r2] * core2[r2,i3,j3]; store fp16*2^14
// per block: one ii (16 W-rows), 64 jj (1024 W-cols), smem-tiled.
// ---------------------------------------------------------------------------
#define T01T_PITCH 68

__global__ __launch_bounds__(256)
void build_w_kernel(const float* __restrict__ c2) {
    __shared__ __align__(16) float c2s[32 * 256];
    __shared__ __align__(16) float t01t[32 * T01T_PITCH];

    const int tid = threadIdx.x;
    const int ii  = blockIdx.y;
    const int jjb = blockIdx.x * 64;

#pragma unroll
    for (int c = tid; c < 2048; c += 256)
        *(float4*)&c2s[c * 4] = *(const float4*)&c2[c * 4];
#pragma unroll
    for (int c = tid; c < 2048; c += 256) {
        int jj = c >> 5, r2 = c & 31;
        t01t[r2 * T01T_PITCH + jj] = g_T01[((size_t)ii * 256 + jjb + jj) * 32 + r2];
    }
    __syncthreads();

    const int jjg = tid >> 4;
    const int i3  = tid & 15;

    float acc[4][16];
#pragma unroll
    for (int a = 0; a < 4; ++a)
#pragma unroll
        for (int b = 0; b < 16; ++b) acc[a][b] = 0.f;

#pragma unroll
    for (int r2 = 0; r2 < 32; ++r2) {
        float4 tv = *(const float4*)&t01t[r2 * T01T_PITCH + jjg * 4];
        const float* crow = &c2s[r2 * 256 + i3 * 16];
        float4 cv0 = *(const float4*)&crow[0];
        float4 cv1 = *(const float4*)&crow[4];
        float4 cv2 = *(const float4*)&crow[8];
        float4 cv3 = *(const float4*)&crow[12];
        float cva[16] = {cv0.x, cv0.y, cv0.z, cv0.w, cv1.x, cv1.y, cv1.z, cv1.w,
                         cv2.x, cv2.y, cv2.z, cv2.w, cv3.x, cv3.y, cv3.z, cv3.w};
        float tva[4] = {tv.x, tv.y, tv.z, tv.w};
#pragma unroll
        for (int a = 0; a < 4; ++a)
#pragma unroll
            for (int b = 0; b < 16; ++b)
                acc[a][b] += tva[a] * cva[b];
    }

    const size_t rowoff = (size_t)(ii * 16 + i3) * 4096;
#pragma unroll
    for (int a = 0; a < 4; ++a) {
        const size_t o = rowoff + (size_t)(jjb + jjg * 4 + a) * 16;
        __half2 buf[8];
#pragma unroll
        for (int p = 0; p < 8; ++p)
            buf[p] = __half2(__float2half(acc[a][2 * p] * WSCALE),
                             __float2half(acc[a][2 * p + 1] * WSCALE));
        *(uint4*)(g_Whf + o)     = *(uint4*)&buf[0];
        *(uint4*)(g_Whf + o + 8) = *(uint4*)&buf[4];
    }
}

// ---------------------------------------------------------------------------
// Kernel 3: X -> fp16
// ---------------------------------------------------------------------------
__global__ void split_x_kernel(const float* __restrict__ x) {
    int idx = blockIdx.x * blockDim.x + threadIdx.x;   // over 1M float4s
    float4 v = ((const float4*)x)[idx];
    __half2* Hp = (__half2*)g_Xhf;
    Hp[idx * 2 + 0] = __half2(__float2half(v.x), __float2half(v.y));
    Hp[idx * 2 + 1] = __half2(__float2half(v.z), __float2half(v.w));
}

// ---------------------------------------------------------------------------
// Kernel 4: fp16 HMMA GEMM. C = (Xhf @ Whf^T) * 2^-14 + bias
// CTA 128x128, BK=64, SW128 swizzle, 3-stage cp.async, 512 threads,
// 2 CTAs/SM. 16 warps = 4(M) x 4(N); warp tile 32x32.
// ---------------------------------------------------------------------------
#define GBM 128
#define GBN 128
#define GBK 64
#define NKT (KDIM / GBK)            // 64
#define ST_A 0
#define ST_B 16384
#define STAGE_BYTES 32768
#define NSTAGE 3
#define SMEM_TOTAL (NSTAGE * STAGE_BYTES)   // 96 KB -> 2 CTAs/SM
#define NTHREADS 512

__device__ __forceinline__ void load_stage(uint32_t st, int bm, int bn,
                                           int kt, int tid) {
    const size_t krow = (size_t)kt * 128;     // byte offset within K row
#pragma unroll
    for (int c = tid; c < 2048; c += NTHREADS) {   // A:1024 + B:1024 chunks
        int arr = c >> 10;                  // 0 = A, 1 = B
        int r   = c & 1023;
        int row = r >> 3, ch = r & 7;
        uint32_t so = (uint32_t)(row * 128 + ch * 16);
        so ^= (so >> 3) & 0x70;
        if (arr == 0) {
            const size_t ga = (size_t)(bm + row) * 8192 + krow + ch * 16;
            cpasync16(st + ST_A + so, (const char*)g_Xhf + ga);
        } else {
            const size_t gb = (size_t)(bn + row) * 8192 + krow + ch * 16;
            cpasync16(st + ST_B + so, (const char*)g_Whf + gb);
        }
    }
}

__global__ __launch_bounds__(NTHREADS, 2)
void gemm_mma_kernel(const float* __restrict__ bias, float* __restrict__ C) {
    extern __shared__ __align__(1024) char smem[];
    const uint32_t sbase = smem_u32(smem);
    const int tid  = threadIdx.x;
    const int lane = tid & 31;
    const int wid  = tid >> 5;
    const int wm = wid & 3;          // 4 M-warps (32 rows each)
    const int wn = wid >> 2;         // 4 N-warps (32 cols each)
    const int bm = blockIdx.y * GBM;
    const int bn = blockIdx.x * GBN;

    const int lrow = lane & 15;
    const uint32_t lchunk = (uint32_t)((lane >> 4) * 16);

    uint32_t a_base[2], a_mask[2];
#pragma unroll
    for (int mt = 0; mt < 2; ++mt) {
        int r = wm * 32 + mt * 16 + lrow;
        a_base[mt] = (uint32_t)(r * 128);
        a_mask[mt] = (uint32_t)((r & 7) << 4);
    }
    uint32_t b_base[2], b_mask[2];
#pragma unroll
    for (int c = 0; c < 2; ++c) {
        int r = wn * 32 + c * 16 + lrow;
        b_base[c] = (uint32_t)(r * 128);
        b_mask[c] = (uint32_t)((r & 7) << 4);
    }

    float acc[2][4][4];
#pragma unroll
    for (int mt = 0; mt < 2; ++mt)
#pragma unroll
        for (int nt = 0; nt < 4; ++nt)
#pragma unroll
            for (int e = 0; e < 4; ++e) acc[mt][nt][e] = 0.f;

    load_stage(sbase + 0 * STAGE_BYTES, bm, bn, 0, tid);
    asm volatile("cp.async.commit_group;" ::: "memory");
    load_stage(sbase + 1 * STAGE_BYTES, bm, bn, 1, tid);
    asm volatile("cp.async.commit_group;" ::: "memory");

    int slot = 0;
    for (int kt = 0; kt < NKT; ++kt) {
        if (kt + 1 < NKT)
            asm volatile("cp.async.wait_group 1;" ::: "memory");
        else
            asm volatile("cp.async.wait_group 0;" ::: "memory");
        __syncthreads();

        if (kt + 2 < NKT) {
            int ns = slot + 2; if (ns >= NSTAGE) ns -= NSTAGE;
            load_stage(sbase + ns * STAGE_BYTES, bm, bn, kt + 2, tid);
            asm volatile("cp.async.commit_group;" ::: "memory");
        }

        const uint32_t st = sbase + slot * STAGE_BYTES;
#pragma unroll
        for (int ks = 0; ks < 4; ++ks) {
            const uint32_t kb = (uint32_t)(ks * 32);
            uint32_t ah[2][4], bh[2][4];
#pragma unroll
            for (int mt = 0; mt < 2; ++mt) {
                uint32_t col = (lchunk + kb) ^ a_mask[mt];
                ldsm4(ah[mt][0], ah[mt][1], ah[mt][2], ah[mt][3],
                      st + ST_A + a_base[mt] + col);
            }
#pragma unroll
            for (int c = 0; c < 2; ++c) {
                uint32_t col = (lchunk + kb) ^ b_mask[c];
                ldsm4(bh[c][0], bh[c][1], bh[c][2], bh[c][3],
                      st + ST_B + b_base[c] + col);
            }
            // 8 independent MMAs (all distinct accumulators)
#pragma unroll
            for (int mt = 0; mt < 2; ++mt)
#pragma unroll
                for (int c = 0; c < 2; ++c)
#pragma unroll
                    for (int o = 0; o < 2; ++o)
                        mma16816(acc[mt][c * 2 + o], ah[mt], bh[c][o], bh[c][o + 2]);
        }
        ++slot; if (slot >= NSTAGE) slot = 0;
    }

    // epilogue: undo 2^14 W scaling (exact), add bias
    const int gq = lane >> 2, rq = lane & 3;
#pragma unroll
    for (int mt = 0; mt < 2; ++mt) {
        const int r0 = bm + wm * 32 + mt * 16 + gq;
#pragma unroll
        for (int nt = 0; nt < 4; ++nt) {
            const int col = bn + wn * 32 + nt * 8 + rq * 2;
            float2 bv = *(const float2*)&bias[col];
            float2 o0 = make_float2(acc[mt][nt][0] * WINV + bv.x,
                                    acc[mt][nt][1] * WINV + bv.y);
            float2 o1 = make_float2(acc[mt][nt][2] * WINV + bv.x,
                                    acc[mt][nt][3] * WINV + bv.y);
            *(float2*)&C[(size_t)r0 * NDIM + col]       = o0;
            *(float2*)&C[(size_t)(r0 + 8) * NDIM + col] = o1;
        }
    }
}

// ---------------------------------------------------------------------------
extern "C" void kernel_launch(void* const* d_in, const int* in_sizes, int n_in,
                              void* d_out, int out_size) {
    const float* x     = (const float*)d_in[0];
    const float* core0 = (const float*)d_in[1];
    const float* core1 = (const float*)d_in[2];
    const float* core2 = (const float*)d_in[3];
    const float* bias  = (const float*)d_in[4];
    float* out = (float*)d_out;

    build_t01_kernel<<<(256 * 256 * 8) / 256, 256>>>(core0, core1);
    build_w_kernel<<<dim3(4, 256), 256>>>(core2);
    split_x_kernel<<<(MDIM * KDIM / 4) / 256, 256>>>(x);

    cudaFuncSetAttribute(gemm_mma_kernel,
                         cudaFuncAttributeMaxDynamicSharedMemorySize, SMEM_TOTAL);
    gemm_mma_kernel<<<dim3(NDIM / GBN, MDIM / GBM), NTHREADS, SMEM_TOTAL>>>(bias, out);
}

// round 10
// speedup vs baseline: 2.0532x; 1.6248x over previous
#include <cuda_runtime.h>
#include <cuda_fp16.h>
#include <cstdint>

// ===========================================================================
// TrainableMPOLayer: y = X @ W^T + bias, W = dense collapse of 3-core MPO.
//   1) T01 = core0 x core1                     (fp32)
//   2) Whf = fp16(W * 2^14)                    (smem-tiled batched GEMM)
//   3) Xhf = fp16(x)
//   4) Y = (Xhf @ Whf^T) * 2^-14 + bias        single-term fp16 HMMA GEMM
// GEMM: CTA 128x128, 256 thr, 8 warps 4Mx2N, warp tile 32x64 (16 MMA / 6
// ldsm per K16 -> 192B ldsm per MMA), BK=64, SW128, 3-stage, 2 CTAs/SM.
// ===========================================================================

#define KDIM 4096
#define MDIM 1024
#define NDIM 4096
#define WSCALE 16384.0f
#define WINV   (1.0f / 16384.0f)

__device__ float   g_T01[256 * 256 * 32];      // 8 MB
__device__ __half  g_Whf[(size_t)4096 * 4096]; // 32 MB (W * 2^14)
__device__ __half  g_Xhf[(size_t)1024 * 4096]; // 8 MB

// ---------------------------------------------------------------------------
// helpers
// ---------------------------------------------------------------------------
__device__ __forceinline__ uint32_t smem_u32(const void* p) {
    uint32_t a;
    asm("{ .reg .u64 t; cvta.to.shared.u64 t, %1; cvt.u32.u64 %0, t; }"
        : "=r"(a) : "l"(p));
    return a;
}

__device__ __forceinline__ void cpasync16(uint32_t dst, const void* src) {
    asm volatile("cp.async.cg.shared.global [%0], [%1], 16;"
                 :: "r"(dst), "l"(src) : "memory");
}

__device__ __forceinline__ void ldsm4(uint32_t& r0, uint32_t& r1,
                                      uint32_t& r2, uint32_t& r3, uint32_t a) {
    asm volatile("ldmatrix.sync.aligned.m8n8.x4.shared.b16 {%0,%1,%2,%3}, [%4];"
                 : "=r"(r0), "=r"(r1), "=r"(r2), "=r"(r3) : "r"(a));
}

__device__ __forceinline__ void mma16816(float* d, const uint32_t* a,
                                         uint32_t b0, uint32_t b1) {
    asm volatile(
        "mma.sync.aligned.m16n8k16.row.col.f32.f16.f16.f32 "
        "{%0,%1,%2,%3}, {%4,%5,%6,%7}, {%8,%9}, {%0,%1,%2,%3};"
        : "+f"(d[0]), "+f"(d[1]), "+f"(d[2]), "+f"(d[3])
        : "r"(a[0]), "r"(a[1]), "r"(a[2]), "r"(a[3]), "r"(b0), "r"(b1));
}

// ---------------------------------------------------------------------------
// Kernel 1: T01[ii, jj, r2] = sum_r1 core0[i1,j1,r1] * core1[r1,i2,j2,r2]
// ---------------------------------------------------------------------------
__global__ void build_t01_kernel(const float* __restrict__ c0,
                                 const float* __restrict__ c1) {
    int idx = blockIdx.x * blockDim.x + threadIdx.x;   // 0 .. 256*256*8-1
    int r2q = idx & 7;
    int jj  = (idx >> 3) & 255;
    int ii  = idx >> 11;
    int j1 = jj >> 4, j2 = jj & 15;
    int i1 = ii >> 4, i2 = ii & 15;

    const float*  a = c0 + (i1 * 16 + j1) * 32;
    const float4* b = (const float4*)(c1 + i2 * 512 + j2 * 32 + r2q * 4);

    float4 s = make_float4(0.f, 0.f, 0.f, 0.f);
#pragma unroll
    for (int r1 = 0; r1 < 32; ++r1) {
        float  av = a[r1];
        float4 bv = b[(size_t)r1 * 2048];
        s.x += av * bv.x; s.y += av * bv.y; s.z += av * bv.z; s.w += av * bv.w;
    }
    *(float4*)(g_T01 + (size_t)idx * 4) = s;
}

// ---------------------------------------------------------------------------
// Kernel 2: W[i,j] = sum_r2 T01[ihi,jhi,r2] * core2[r2,i3,j3]; store fp16*2^14
// ---------------------------------------------------------------------------
#define T01T_PITCH 68

__global__ __launch_bounds__(256)
void build_w_kernel(const float* __restrict__ c2) {
    __shared__ __align__(16) float c2s[32 * 256];
    __shared__ __align__(16) float t01t[32 * T01T_PITCH];

    const int tid = threadIdx.x;
    const int ii  = blockIdx.y;
    const int jjb = blockIdx.x * 64;

#pragma unroll
    for (int c = tid; c < 2048; c += 256)
        *(float4*)&c2s[c * 4] = *(const float4*)&c2[c * 4];
#pragma unroll
    for (int c = tid; c < 2048; c += 256) {
        int jj = c >> 5, r2 = c & 31;
        t01t[r2 * T01T_PITCH + jj] = g_T01[((size_t)ii * 256 + jjb + jj) * 32 + r2];
    }
    __syncthreads();

    const int jjg = tid >> 4;
    const int i3  = tid & 15;

    float acc[4][16];
#pragma unroll
    for (int a = 0; a < 4; ++a)
#pragma unroll
        for (int b = 0; b < 16; ++b) acc[a][b] = 0.f;

#pragma unroll
    for (int r2 = 0; r2 < 32; ++r2) {
        float4 tv = *(const float4*)&t01t[r2 * T01T_PITCH + jjg * 4];
        const float* crow = &c2s[r2 * 256 + i3 * 16];
        float4 cv0 = *(const float4*)&crow[0];
        float4 cv1 = *(const float4*)&crow[4];
        float4 cv2 = *(const float4*)&crow[8];
        float4 cv3 = *(const float4*)&crow[12];
        float cva[16] = {cv0.x, cv0.y, cv0.z, cv0.w, cv1.x, cv1.y, cv1.z, cv1.w,
                         cv2.x, cv2.y, cv2.z, cv2.w, cv3.x, cv3.y, cv3.z, cv3.w};
        float tva[4] = {tv.x, tv.y, tv.z, tv.w};
#pragma unroll
        for (int a = 0; a < 4; ++a)
#pragma unroll
            for (int b = 0; b < 16; ++b)
                acc[a][b] += tva[a] * cva[b];
    }

    const size_t rowoff = (size_t)(ii * 16 + i3) * 4096;
#pragma unroll
    for (int a = 0; a < 4; ++a) {
        const size_t o = rowoff + (size_t)(jjb + jjg * 4 + a) * 16;
        __half2 buf[8];
#pragma unroll
        for (int p = 0; p < 8; ++p)
            buf[p] = __half2(__float2half(acc[a][2 * p] * WSCALE),
                             __float2half(acc[a][2 * p + 1] * WSCALE));
        *(uint4*)(g_Whf + o)     = *(uint4*)&buf[0];
        *(uint4*)(g_Whf + o + 8) = *(uint4*)&buf[4];
    }
}

// ---------------------------------------------------------------------------
// Kernel 3: X -> fp16
// ---------------------------------------------------------------------------
__global__ void split_x_kernel(const float* __restrict__ x) {
    int idx = blockIdx.x * blockDim.x + threadIdx.x;   // over 1M float4s
    float4 v = ((const float4*)x)[idx];
    __half2* Hp = (__half2*)g_Xhf;
    Hp[idx * 2 + 0] = __half2(__float2half(v.x), __float2half(v.y));
    Hp[idx * 2 + 1] = __half2(__float2half(v.z), __float2half(v.w));
}

// ---------------------------------------------------------------------------
// Kernel 4: fp16 HMMA GEMM. C = (Xhf @ Whf^T) * 2^-14 + bias
// CTA 128x128, BK=64, SW128 swizzle, 3-stage cp.async, 256 threads.
// 8 warps = 4(M) x 2(N); warp tile 32x64. 2 CTAs/SM.
// ---------------------------------------------------------------------------
#define GBM 128
#define GBN 128
#define GBK 64
#define NKT (KDIM / GBK)            // 64
#define ST_A 0
#define ST_B 16384
#define STAGE_BYTES 32768
#define NSTAGE 3
#define SMEM_TOTAL (NSTAGE * STAGE_BYTES)   // 96 KB -> 2 CTAs/SM
#define NTHREADS 256

__device__ __forceinline__ void load_stage(uint32_t st, int bm, int bn,
                                           int kt, int tid) {
    const size_t krow = (size_t)kt * 128;     // byte offset within K row
#pragma unroll
    for (int c = tid; c < 2048; c += NTHREADS) {   // A:1024 + B:1024 chunks
        int arr = c >> 10;                  // 0 = A, 1 = B
        int r   = c & 1023;
        int row = r >> 3, ch = r & 7;
        uint32_t so = (uint32_t)(row * 128 + ch * 16);
        so ^= (so >> 3) & 0x70;
        if (arr == 0) {
            const size_t ga = (size_t)(bm + row) * 8192 + krow + ch * 16;
            cpasync16(st + ST_A + so, (const char*)g_Xhf + ga);
        } else {
            const size_t gb = (size_t)(bn + row) * 8192 + krow + ch * 16;
            cpasync16(st + ST_B + so, (const char*)g_Whf + gb);
        }
    }
}

__global__ __launch_bounds__(NTHREADS)
void gemm_mma_kernel(const float* __restrict__ bias, float* __restrict__ C) {
    extern __shared__ __align__(1024) char smem[];
    const uint32_t sbase = smem_u32(smem);
    const int tid  = threadIdx.x;
    const int lane = tid & 31;
    const int wid  = tid >> 5;
    const int wm = wid & 3;          // 4 M-warps (32 rows each)
    const int wn = wid >> 2;         // 2 N-warps (64 cols each)
    const int bm = blockIdx.y * GBM;
    const int bn = blockIdx.x * GBN;

    const int lrow = lane & 15;
    const uint32_t lchunk = (uint32_t)((lane >> 4) * 16);

    // A tiles: rows wm*32 + mt*16 + lrow
    uint32_t a_base[2], a_mask[2];
#pragma unroll
    for (int mt = 0; mt < 2; ++mt) {
        int r = wm * 32 + mt * 16 + lrow;
        a_base[mt] = (uint32_t)(r * 128);
        a_mask[mt] = (uint32_t)((r & 7) << 4);
    }
    // B n16-chunks: rows wn*64 + c*16 + lrow
    uint32_t b_base[4], b_mask[4];
#pragma unroll
    for (int c = 0; c < 4; ++c) {
        int r = wn * 64 + c * 16 + lrow;
        b_base[c] = (uint32_t)(r * 128);
        b_mask[c] = (uint32_t)((r & 7) << 4);
    }

    float acc[2][8][4];
#pragma unroll
    for (int mt = 0; mt < 2; ++mt)
#pragma unroll
        for (int nt = 0; nt < 8; ++nt)
#pragma unroll
            for (int e = 0; e < 4; ++e) acc[mt][nt][e] = 0.f;

    load_stage(sbase + 0 * STAGE_BYTES, bm, bn, 0, tid);
    asm volatile("cp.async.commit_group;" ::: "memory");
    load_stage(sbase + 1 * STAGE_BYTES, bm, bn, 1, tid);
    asm volatile("cp.async.commit_group;" ::: "memory");

    int slot = 0;
    for (int kt = 0; kt < NKT; ++kt) {
        if (kt + 1 < NKT)
            asm volatile("cp.async.wait_group 1;" ::: "memory");
        else
            asm volatile("cp.async.wait_group 0;" ::: "memory");
        __syncthreads();

        if (kt + 2 < NKT) {
            int ns = slot + 2; if (ns >= NSTAGE) ns -= NSTAGE;
            load_stage(sbase + ns * STAGE_BYTES, bm, bn, kt + 2, tid);
            asm volatile("cp.async.commit_group;" ::: "memory");
        }

        const uint32_t st = sbase + slot * STAGE_BYTES;
#pragma unroll
        for (int ks = 0; ks < 4; ++ks) {
            const uint32_t kb = (uint32_t)(ks * 32);
            uint32_t ah[2][4];
#pragma unroll
            for (int mt = 0; mt < 2; ++mt) {
                uint32_t col = (lchunk + kb) ^ a_mask[mt];
                ldsm4(ah[mt][0], ah[mt][1], ah[mt][2], ah[mt][3],
                      st + ST_A + a_base[mt] + col);
            }
#pragma unroll
            for (int c = 0; c < 4; ++c) {
                uint32_t col = (lchunk + kb) ^ b_mask[c];
                uint32_t bh[4];
                ldsm4(bh[0], bh[1], bh[2], bh[3], st + ST_B + b_base[c] + col);
#pragma unroll
                for (int mt = 0; mt < 2; ++mt)
#pragma unroll
                    for (int o = 0; o < 2; ++o)
                        mma16816(acc[mt][c * 2 + o], ah[mt], bh[o], bh[o + 2]);
            }
        }
        ++slot; if (slot >= NSTAGE) slot = 0;
    }

    // epilogue: undo 2^14 W scaling (exact), add bias
    const int gq = lane >> 2, rq = lane & 3;
#pragma unroll
    for (int mt = 0; mt < 2; ++mt) {
        const int r0 = bm + wm * 32 + mt * 16 + gq;
#pragma unroll
        for (int nt = 0; nt < 8; ++nt) {
            const int col = bn + wn * 64 + nt * 8 + rq * 2;
            float2 bv = *(const float2*)&bias[col];
            float2 o0 = make_float2(acc[mt][nt][0] * WINV + bv.x,
                                    acc[mt][nt][1] * WINV + bv.y);
            float2 o1 = make_float2(acc[mt][nt][2] * WINV + bv.x,
                                    acc[mt][nt][3] * WINV + bv.y);
            *(float2*)&C[(size_t)r0 * NDIM + col]       = o0;
            *(float2*)&C[(size_t)(r0 + 8) * NDIM + col] = o1;
        }
    }
}

// ---------------------------------------------------------------------------
extern "C" void kernel_launch(void* const* d_in, const int* in_sizes, int n_in,
                              void* d_out, int out_size) {
    const float* x     = (const float*)d_in[0];
    const float* core0 = (const float*)d_in[1];
    const float* core1 = (const float*)d_in[2];
    const float* core2 = (const float*)d_in[3];
    const float* bias  = (const float*)d_in[4];
    float* out = (float*)d_out;

    build_t01_kernel<<<(256 * 256 * 8) / 256, 256>>>(core0, core1);
    build_w_kernel<<<dim3(4, 256), 256>>>(core2);
    split_x_kernel<<<(MDIM * KDIM / 4) / 256, 256>>>(x);

    cudaFuncSetAttribute(gemm_mma_kernel,
                         cudaFuncAttributeMaxDynamicSharedMemorySize, SMEM_TOTAL);
    gemm_mma_kernel<<<dim3(NDIM / GBN, MDIM / GBM), NTHREADS, SMEM_TOTAL>>>(bias, out);
}

// round 11
// speedup vs baseline: 2.5398x; 1.2370x over previous
#include <cuda_runtime.h>
#include <cuda_fp16.h>
#include <cstdint>

// ===========================================================================
// TrainableMPOLayer: y = X @ W^T + bias, W = dense collapse of 3-core MPO.
//   1) T01 = core0 x core1     (fp32; 4 j1-outputs/thread, shared b column)
//   2) Whf = fp16(W * 2^14)    (smem-tiled; broadcast c2 reads, no conflicts)
//   3) Xhf = fp16(x)
//   4) Y = (Xhf @ Whf^T) * 2^-14 + bias   single-term fp16 HMMA GEMM
// ===========================================================================

#define KDIM 4096
#define MDIM 1024
#define NDIM 4096
#define WSCALE 16384.0f
#define WINV   (1.0f / 16384.0f)

__device__ float   g_T01[256 * 256 * 32];      // 8 MB
__device__ __half  g_Whf[(size_t)4096 * 4096]; // 32 MB (W * 2^14)
__device__ __half  g_Xhf[(size_t)1024 * 4096]; // 8 MB

// ---------------------------------------------------------------------------
// helpers
// ---------------------------------------------------------------------------
__device__ __forceinline__ uint32_t smem_u32(const void* p) {
    uint32_t a;
    asm("{ .reg .u64 t; cvta.to.shared.u64 t, %1; cvt.u32.u64 %0, t; }"
        : "=r"(a) : "l"(p));
    return a;
}

__device__ __forceinline__ void cpasync16(uint32_t dst, const void* src) {
    asm volatile("cp.async.cg.shared.global [%0], [%1], 16;"
                 :: "r"(dst), "l"(src) : "memory");
}

__device__ __forceinline__ void ldsm4(uint32_t& r0, uint32_t& r1,
                                      uint32_t& r2, uint32_t& r3, uint32_t a) {
    asm volatile("ldmatrix.sync.aligned.m8n8.x4.shared.b16 {%0,%1,%2,%3}, [%4];"
                 : "=r"(r0), "=r"(r1), "=r"(r2), "=r"(r3) : "r"(a));
}

__device__ __forceinline__ void mma16816(float* d, const uint32_t* a,
                                         uint32_t b0, uint32_t b1) {
    asm volatile(
        "mma.sync.aligned.m16n8k16.row.col.f32.f16.f16.f32 "
        "{%0,%1,%2,%3}, {%4,%5,%6,%7}, {%8,%9}, {%0,%1,%2,%3};"
        : "+f"(d[0]), "+f"(d[1]), "+f"(d[2]), "+f"(d[3])
        : "r"(a[0]), "r"(a[1]), "r"(a[2]), "r"(a[3]), "r"(b0), "r"(b1));
}

// ---------------------------------------------------------------------------
// Kernel 1: T01[ii, jj, r2] = sum_r1 core0[i1,j1,r1] * core1[r1,i2,j2,r2]
// Each thread: 4 j1 values x 1 (j2, r2-quad) -> b column loaded ONCE.
// ---------------------------------------------------------------------------
__global__ void build_t01_kernel(const float* __restrict__ c0,
                                 const float* __restrict__ c1) {
    int idx = blockIdx.x * blockDim.x + threadIdx.x;   // 0 .. 131071
    int r2q = idx & 7;
    int j2  = (idx >> 3) & 15;
    int j1g = (idx >> 7) & 3;          // j1 = j1g*4 + v
    int ii  = idx >> 9;                // 0..255
    int i1 = ii >> 4, i2 = ii & 15;

    const float4* b = (const float4*)(c1 + i2 * 512 + j2 * 32 + r2q * 4);
    const float*  a = c0 + (i1 * 16 + j1g * 4) * 32;   // 4 rows of 32

    float4 s[4];
#pragma unroll
    for (int v = 0; v < 4; ++v) s[v] = make_float4(0.f, 0.f, 0.f, 0.f);

#pragma unroll
    for (int r1 = 0; r1 < 32; ++r1) {
        float4 bv = b[(size_t)r1 * 2048];
#pragma unroll
        for (int v = 0; v < 4; ++v) {
            float av = a[v * 32 + r1];
            s[v].x += av * bv.x; s[v].y += av * bv.y;
            s[v].z += av * bv.z; s[v].w += av * bv.w;
        }
    }
#pragma unroll
    for (int v = 0; v < 4; ++v) {
        int jj = (j1g * 4 + v) * 16 + j2;
        *(float4*)(g_T01 + ((size_t)ii * 256 + jj) * 32 + r2q * 4) = s[v];
    }
}

// ---------------------------------------------------------------------------
// Kernel 2: W[i,j] = sum_r2 T01[ihi,jhi,r2] * core2[r2,i3,j3]; store fp16*2^14
// Thread map: i3 = tid>>4 (c2 reads broadcast), jjg = tid&15 (t01t coalesced).
// ---------------------------------------------------------------------------
#define T01T_PITCH 68

__global__ __launch_bounds__(256)
void build_w_kernel(const float* __restrict__ c2) {
    __shared__ __align__(16) float c2s[32 * 256];
    __shared__ __align__(16) float t01t[32 * T01T_PITCH];

    const int tid = threadIdx.x;
    const int ii  = blockIdx.y;
    const int jjb = blockIdx.x * 64;

#pragma unroll
    for (int c = tid; c < 2048; c += 256)
        *(float4*)&c2s[c * 4] = *(const float4*)&c2[c * 4];
#pragma unroll
    for (int c = tid; c < 2048; c += 256) {
        int jj = c >> 5, r2 = c & 31;
        t01t[r2 * T01T_PITCH + jj] = g_T01[((size_t)ii * 256 + jjb + jj) * 32 + r2];
    }
    __syncthreads();

    const int i3  = tid >> 4;   // 0..15: half-warp shares i3 -> c2 broadcast
    const int jjg = tid & 15;   // 0..15: consecutive lanes -> coalesced t01t

    float acc[4][16];
#pragma unroll
    for (int a = 0; a < 4; ++a)
#pragma unroll
        for (int b = 0; b < 16; ++b) acc[a][b] = 0.f;

#pragma unroll
    for (int r2 = 0; r2 < 32; ++r2) {
        float4 tv = *(const float4*)&t01t[r2 * T01T_PITCH + jjg * 4];
        const float* crow = &c2s[r2 * 256 + i3 * 16];
        float4 cv0 = *(const float4*)&crow[0];
        float4 cv1 = *(const float4*)&crow[4];
        float4 cv2 = *(const float4*)&crow[8];
        float4 cv3 = *(const float4*)&crow[12];
        float cva[16] = {cv0.x, cv0.y, cv0.z, cv0.w, cv1.x, cv1.y, cv1.z, cv1.w,
                         cv2.x, cv2.y, cv2.z, cv2.w, cv3.x, cv3.y, cv3.z, cv3.w};
        float tva[4] = {tv.x, tv.y, tv.z, tv.w};
#pragma unroll
        for (int a = 0; a < 4; ++a)
#pragma unroll
            for (int b = 0; b < 16; ++b)
                acc[a][b] += tva[a] * cva[b];
    }

    const size_t rowoff = (size_t)(ii * 16 + i3) * 4096;
#pragma unroll
    for (int a = 0; a < 4; ++a) {
        const size_t o = rowoff + (size_t)(jjb + jjg * 4 + a) * 16;
        __half2 buf[8];
#pragma unroll
        for (int p = 0; p < 8; ++p)
            buf[p] = __half2(__float2half(acc[a][2 * p] * WSCALE),
                             __float2half(acc[a][2 * p + 1] * WSCALE));
        *(uint4*)(g_Whf + o)     = *(uint4*)&buf[0];
        *(uint4*)(g_Whf + o + 8) = *(uint4*)&buf[4];
    }
}

// ---------------------------------------------------------------------------
// Kernel 3: X -> fp16
// ---------------------------------------------------------------------------
__global__ void split_x_kernel(const float* __restrict__ x) {
    int idx = blockIdx.x * blockDim.x + threadIdx.x;   // over 1M float4s
    float4 v = ((const float4*)x)[idx];
    __half2* Hp = (__half2*)g_Xhf;
    Hp[idx * 2 + 0] = __half2(__float2half(v.x), __float2half(v.y));
    Hp[idx * 2 + 1] = __half2(__float2half(v.z), __float2half(v.w));
}

// ---------------------------------------------------------------------------
// Kernel 4: fp16 HMMA GEMM. C = (Xhf @ Whf^T) * 2^-14 + bias
// CTA 128x128, BK=64, SW128 swizzle, 3-stage cp.async, 256 threads.
// 8 warps = 4(M) x 2(N); warp tile 32x64. 2 CTAs/SM.
// ---------------------------------------------------------------------------
#define GBM 128
#define GBN 128
#define GBK 64
#define NKT (KDIM / GBK)            // 64
#define ST_A 0
#define ST_B 16384
#define STAGE_BYTES 32768
#define NSTAGE 3
#define SMEM_TOTAL (NSTAGE * STAGE_BYTES)   // 96 KB -> 2 CTAs/SM
#define NTHREADS 256

__device__ __forceinline__ void load_stage(uint32_t st, int bm, int bn,
                                           int kt, int tid) {
    const size_t krow = (size_t)kt * 128;     // byte offset within K row
#pragma unroll
    for (int c = tid; c < 2048; c += NTHREADS) {   // A:1024 + B:1024 chunks
        int arr = c >> 10;                  // 0 = A, 1 = B
        int r   = c & 1023;
        int row = r >> 3, ch = r & 7;
        uint32_t so = (uint32_t)(row * 128 + ch * 16);
        so ^= (so >> 3) & 0x70;
        if (arr == 0) {
            const size_t ga = (size_t)(bm + row) * 8192 + krow + ch * 16;
            cpasync16(st + ST_A + so, (const char*)g_Xhf + ga);
        } else {
            const size_t gb = (size_t)(bn + row) * 8192 + krow + ch * 16;
            cpasync16(st + ST_B + so, (const char*)g_Whf + gb);
        }
    }
}

__global__ __launch_bounds__(NTHREADS)
void gemm_mma_kernel(const float* __restrict__ bias, float* __restrict__ C) {
    extern __shared__ __align__(1024) char smem[];
    const uint32_t sbase = smem_u32(smem);
    const int tid  = threadIdx.x;
    const int lane = tid & 31;
    const int wid  = tid >> 5;
    const int wm = wid & 3;          // 4 M-warps (32 rows each)
    const int wn = wid >> 2;         // 2 N-warps (64 cols each)
    const int bm = blockIdx.y * GBM;
    const int bn = blockIdx.x * GBN;

    const int lrow = lane & 15;
    const uint32_t lchunk = (uint32_t)((lane >> 4) * 16);

    uint32_t a_base[2], a_mask[2];
#pragma unroll
    for (int mt = 0; mt < 2; ++mt) {
        int r = wm * 32 + mt * 16 + lrow;
        a_base[mt] = (uint32_t)(r * 128);
        a_mask[mt] = (uint32_t)((r & 7) << 4);
    }
    uint32_t b_base[4], b_mask[4];
#pragma unroll
    for (int c = 0; c < 4; ++c) {
        int r = wn * 64 + c * 16 + lrow;
        b_base[c] = (uint32_t)(r * 128);
        b_mask[c] = (uint32_t)((r & 7) << 4);
    }

    float acc[2][8][4];
#pragma unroll
    for (int mt = 0; mt < 2; ++mt)
#pragma unroll
        for (int nt = 0; nt < 8; ++nt)
#pragma unroll
            for (int e = 0; e < 4; ++e) acc[mt][nt][e] = 0.f;

    load_stage(sbase + 0 * STAGE_BYTES, bm, bn, 0, tid);
    asm volatile("cp.async.commit_group;" ::: "memory");
    load_stage(sbase + 1 * STAGE_BYTES, bm, bn, 1, tid);
    asm volatile("cp.async.commit_group;" ::: "memory");

    int slot = 0;
    for (int kt = 0; kt < NKT; ++kt) {
        if (kt + 1 < NKT)
            asm volatile("cp.async.wait_group 1;" ::: "memory");
        else
            asm volatile("cp.async.wait_group 0;" ::: "memory");
        __syncthreads();

        if (kt + 2 < NKT) {
            int ns = slot + 2; if (ns >= NSTAGE) ns -= NSTAGE;
            load_stage(sbase + ns * STAGE_BYTES, bm, bn, kt + 2, tid);
            asm volatile("cp.async.commit_group;" ::: "memory");
        }

        const uint32_t st = sbase + slot * STAGE_BYTES;
#pragma unroll
        for (int ks = 0; ks < 4; ++ks) {
            const uint32_t kb = (uint32_t)(ks * 32);
            uint32_t ah[2][4];
#pragma unroll
            for (int mt = 0; mt < 2; ++mt) {
                uint32_t col = (lchunk + kb) ^ a_mask[mt];
                ldsm4(ah[mt][0], ah[mt][1], ah[mt][2], ah[mt][3],
                      st + ST_A + a_base[mt] + col);
            }
#pragma unroll
            for (int c = 0; c < 4; ++c) {
                uint32_t col = (lchunk + kb) ^ b_mask[c];
                uint32_t bh[4];
                ldsm4(bh[0], bh[1], bh[2], bh[3], st + ST_B + b_base[c] + col);
#pragma unroll
                for (int mt = 0; mt < 2; ++mt)
#pragma unroll
                    for (int o = 0; o < 2; ++o)
                        mma16816(acc[mt][c * 2 + o], ah[mt], bh[o], bh[o + 2]);
            }
        }
        ++slot; if (slot >= NSTAGE) slot = 0;
    }

    // epilogue: undo 2^14 W scaling (exact), add bias
    const int gq = lane >> 2, rq = lane & 3;
#pragma unroll
    for (int mt = 0; mt < 2; ++mt) {
        const int r0 = bm + wm * 32 + mt * 16 + gq;
#pragma unroll
        for (int nt = 0; nt < 8; ++nt) {
            const int col = bn + wn * 64 + nt * 8 + rq * 2;
            float2 bv = *(const float2*)&bias[col];
            float2 o0 = make_float2(acc[mt][nt][0] * WINV + bv.x,
                                    acc[mt][nt][1] * WINV + bv.y);
            float2 o1 = make_float2(acc[mt][nt][2] * WINV + bv.x,
                                    acc[mt][nt][3] * WINV + bv.y);
            *(float2*)&C[(size_t)r0 * NDIM + col]       = o0;
            *(float2*)&C[(size_t)(r0 + 8) * NDIM + col] = o1;
        }
    }
}

// ---------------------------------------------------------------------------
extern "C" void kernel_launch(void* const* d_in, const int* in_sizes, int n_in,
                              void* d_out, int out_size) {
    const float* x     = (const float*)d_in[0];
    const float* core0 = (const float*)d_in[1];
    const float* core1 = (const float*)d_in[2];
    const float* core2 = (const float*)d_in[3];
    const float* bias  = (const float*)d_in[4];
    float* out = (float*)d_out;

    build_t01_kernel<<<512, 256>>>(core0, core1);
    build_w_kernel<<<dim3(4, 256), 256>>>(core2);
    split_x_kernel<<<(MDIM * KDIM / 4) / 256, 256>>>(x);

    cudaFuncSetAttribute(gemm_mma_kernel,
                         cudaFuncAttributeMaxDynamicSharedMemorySize, SMEM_TOTAL);
    gemm_mma_kernel<<<dim3(NDIM / GBN, MDIM / GBM), NTHREADS, SMEM_TOTAL>>>(bias, out);
}